// round 3
// baseline (speedup 1.0000x reference)
#include <cuda_runtime.h>
#include <cuda_bf16.h>
#include <cstdint>

// ============================================================================
// Problem constants
// ============================================================================
#define T_TOK   8192        // B*S
#define D_IN    4096
#define D_OUT   4096
#define N_EXP   8
#define RANK    16
#define KEXTRA  128         // E*R
#define KSTR    4224        // D_IN + KEXTRA (extended K)
#define SCALING 2.0f

// ============================================================================
// Persistent device scratch (static arrays: allocation-free)
// x/W pre-split into bf16 hi/lo planes over extended K (lora cols appended)
// ============================================================================
__device__ __nv_bfloat16 g_xh[(size_t)T_TOK * KSTR];
__device__ __nv_bfloat16 g_xl[(size_t)T_TOK * KSTR];
__device__ __nv_bfloat16 g_Wh[(size_t)D_OUT * KSTR];
__device__ __nv_bfloat16 g_Wl[(size_t)D_OUT * KSTR];
__device__ float g_dummy_rw[2 * T_TOK * N_EXP];

// ============================================================================
// Helpers (sm_80-compatible PTX only — NO 'a'-suffix features; ptxas targets
// plain sm_103 where tcgen05/TMEM are rejected)
// ============================================================================
__device__ __forceinline__ uint32_t smem_to_u32(const void* p) {
    uint32_t a;
    asm("{ .reg .u64 t; cvta.to.shared.u64 t, %1; cvt.u32.u64 %0, t; }" : "=r"(a) : "l"(p));
    return a;
}
__device__ __forceinline__ void cpasync16(uint32_t saddr, const void* g) {
    asm volatile("cp.async.cg.shared.global [%0], [%1], 16;" :: "r"(saddr), "l"(g));
}
__device__ __forceinline__ void cp_commit() {
    asm volatile("cp.async.commit_group;" ::: "memory");
}
__device__ __forceinline__ void ldsm4(uint32_t* r, uint32_t addr) {
    asm volatile("ldmatrix.sync.aligned.m8n8.x4.shared.b16 {%0,%1,%2,%3}, [%4];"
                 : "=r"(r[0]), "=r"(r[1]), "=r"(r[2]), "=r"(r[3]) : "r"(addr));
}
__device__ __forceinline__ void mma16816(float* c, const uint32_t* a, const uint32_t* b) {
    asm volatile(
        "mma.sync.aligned.m16n8k16.row.col.f32.bf16.bf16.f32 "
        "{%0,%1,%2,%3}, {%4,%5,%6,%7}, {%8,%9}, {%0,%1,%2,%3};"
        : "+f"(c[0]), "+f"(c[1]), "+f"(c[2]), "+f"(c[3])
        : "r"(a[0]), "r"(a[1]), "r"(a[2]), "r"(a[3]), "r"(b[0]), "r"(b[1]));
}
__device__ __forceinline__ uint32_t pack_bf16(float a, float b) {
    __nv_bfloat16 ha = __float2bfloat16_rn(a);
    __nv_bfloat16 hb = __float2bfloat16_rn(b);
    return (uint32_t)__bfloat16_as_ushort(ha) | ((uint32_t)__bfloat16_as_ushort(hb) << 16);
}

// ============================================================================
// Kernel 1: router + expert-h (pure fp32; gate_score is a checked output).
// Computes gate_score, routing_weight and writes the gated/scaled lora
// activation g = SCALING*rw*h directly into the lora columns of g_xh/g_xl.
// ============================================================================
#define K1_TOKS   64
#define K1_NDOT   136
#define K1_XS_STRIDE 65
#define K1_WS_STRIDE 68
#define K1_WS_ROWS   144
#define K1_XS_OFF 0
#define K1_WS_OFF (K1_TOKS * K1_XS_STRIDE)
#define K1_RW_OFF (K1_WS_OFF + K1_WS_ROWS * K1_WS_STRIDE)
#define K1_SMEM_FLOATS (K1_RW_OFF + K1_TOKS * N_EXP)
#define K1_SMEM_BYTES (K1_SMEM_FLOATS * 4)

__global__ void __launch_bounds__(256) router_kernel(
    const float* __restrict__ x, const float* __restrict__ routeW,
    const float* __restrict__ loraA, float* __restrict__ out_rw,
    float* __restrict__ out_gs)
{
    extern __shared__ float sm[];
    float* xsT = sm + K1_XS_OFF;
    float* ws  = sm + K1_WS_OFF;
    float* rws = sm + K1_RW_OFF;

    const int tid = threadIdx.x;
    const int ti = tid & 15;
    const int tj = tid >> 4;
    const int tok0 = blockIdx.x * K1_TOKS;

    float acc[4][9];
#pragma unroll
    for (int u = 0; u < 4; ++u)
#pragma unroll
        for (int v = 0; v < 9; ++v) acc[u][v] = 0.0f;

    for (int kb = 0; kb < D_IN / 64; ++kb) {
#pragma unroll
        for (int i = 0; i < 4; ++i) {
            int f = tid + 256 * i;
            int tr = f >> 4, c4 = f & 15;
            float4 v = *(const float4*)(x + (size_t)(tok0 + tr) * D_IN + kb * 64 + c4 * 4);
            int k0 = c4 * 4;
            xsT[(k0 + 0) * K1_XS_STRIDE + tr] = v.x;
            xsT[(k0 + 1) * K1_XS_STRIDE + tr] = v.y;
            xsT[(k0 + 2) * K1_XS_STRIDE + tr] = v.z;
            xsT[(k0 + 3) * K1_XS_STRIDE + tr] = v.w;
        }
#pragma unroll
        for (int i = 0; i < 9; ++i) {
            int f = tid + 256 * i;
            if (f < K1_NDOT * 16) {
                int j = f >> 4, c4 = f & 15;
                const float* src = (j < N_EXP) ? (routeW + (size_t)j * D_IN)
                                               : (loraA + (size_t)(j - N_EXP) * D_IN);
                float4 v = *(const float4*)(src + kb * 64 + c4 * 4);
                *(float4*)(ws + j * K1_WS_STRIDE + c4 * 4) = v;
            }
        }
        __syncthreads();
#pragma unroll 4
        for (int k = 0; k < 64; ++k) {
            float xv[4], wv[9];
#pragma unroll
            for (int u = 0; u < 4; ++u) xv[u] = xsT[k * K1_XS_STRIDE + ti * 4 + u];
#pragma unroll
            for (int v = 0; v < 9; ++v) wv[v] = ws[(tj * 9 + v) * K1_WS_STRIDE + k];
#pragma unroll
            for (int u = 0; u < 4; ++u)
#pragma unroll
                for (int v = 0; v < 9; ++v)
                    acc[u][v] = fmaf(xv[u], wv[v], acc[u][v]);
        }
        __syncthreads();
    }

    float* hg = ws;   // reuse, stride 137
#pragma unroll
    for (int u = 0; u < 4; ++u)
#pragma unroll
        for (int v = 0; v < 9; ++v) {
            int j = tj * 9 + v;
            if (j < K1_NDOT) hg[(ti * 4 + u) * 137 + j] = acc[u][v];
        }
    __syncthreads();

    if (tid < K1_TOKS) {
        const float* h = hg + tid * 137;
        float g[N_EXP], m = -1e30f;
#pragma unroll
        for (int j = 0; j < N_EXP; ++j) { g[j] = h[j]; m = fmaxf(m, g[j]); }
        float p[N_EXP], s = 0.0f;
#pragma unroll
        for (int j = 0; j < N_EXP; ++j) { p[j] = expf(g[j] - m); s += p[j]; }
        float inv = 1.0f / s;
#pragma unroll
        for (int j = 0; j < N_EXP; ++j) p[j] *= inv;

        int i1 = 0;
#pragma unroll
        for (int j = 1; j < N_EXP; ++j) if (p[j] > p[i1]) i1 = j;
        int i2 = (i1 == 0) ? 1 : 0;
#pragma unroll
        for (int j = 0; j < N_EXP; ++j) if (j != i1 && p[j] > p[i2]) i2 = j;

        float denom = p[i1] + p[i2] + 1e-9f;
        float w1 = p[i1] / denom, w2 = p[i2] / denom;

        size_t ob = (size_t)(tok0 + tid) * N_EXP;
#pragma unroll
        for (int j = 0; j < N_EXP; ++j) {
            out_gs[ob + j] = g[j];
            float w = (j == i1) ? w1 : ((j == i2) ? w2 : 0.0f);
            out_rw[ob + j] = w;
            rws[tid * N_EXP + j] = w;
        }
    }
    __syncthreads();

    // lora activation columns (K in [4096,4224)) of xh/xl
#pragma unroll
    for (int i = 0; i < 32; ++i) {
        int idx = tid + 256 * i;                 // 64 tok * 128 cols
        int t = idx >> 7, kk = idx & 127;
        float val = SCALING * rws[t * N_EXP + (kk >> 4)] * hg[t * 137 + N_EXP + kk];
        __nv_bfloat16 hi = __float2bfloat16_rn(val);
        size_t o = (size_t)(tok0 + t) * KSTR + D_IN + kk;
        g_xh[o] = hi;
        g_xl[o] = __float2bfloat16_rn(val - __bfloat162float(hi));
    }
}

// ============================================================================
// Kernel 1b: pack lora_B[E, D_OUT, R] -> lora columns of Wh/Wl
// ============================================================================
__global__ void packL_kernel(const float* __restrict__ loraB) {
    int idx = blockIdx.x * 256 + threadIdx.x;   // D_OUT*KEXTRA
    int o = idx >> 7, kk = idx & 127;
    int e = kk >> 4, r = kk & 15;
    float val = loraB[((size_t)e * D_OUT + o) * RANK + r];
    __nv_bfloat16 hi = __float2bfloat16_rn(val);
    size_t p = (size_t)o * KSTR + D_IN + kk;
    g_Wh[p] = hi;
    g_Wl[p] = __float2bfloat16_rn(val - __bfloat162float(hi));
}

// ============================================================================
// Kernel 1c/1d: split fp32 -> bf16 hi/lo planes (main K region)
// ============================================================================
__device__ __forceinline__ void split_store(const float* src, __nv_bfloat16* dh,
                                            __nv_bfloat16* dl, size_t ridx, int c4,
                                            int src_stride) {
    float4 v = *(const float4*)(src + ridx * src_stride + c4 * 4);
    __nv_bfloat16 h0 = __float2bfloat16_rn(v.x);
    __nv_bfloat16 h1 = __float2bfloat16_rn(v.y);
    __nv_bfloat16 h2 = __float2bfloat16_rn(v.z);
    __nv_bfloat16 h3 = __float2bfloat16_rn(v.w);
    uint2 hi, lo;
    hi.x = (uint32_t)__bfloat16_as_ushort(h0) | ((uint32_t)__bfloat16_as_ushort(h1) << 16);
    hi.y = (uint32_t)__bfloat16_as_ushort(h2) | ((uint32_t)__bfloat16_as_ushort(h3) << 16);
    lo.x = pack_bf16(v.x - __bfloat162float(h0), v.y - __bfloat162float(h1));
    lo.y = pack_bf16(v.z - __bfloat162float(h2), v.w - __bfloat162float(h3));
    *(uint2*)(dh + ridx * KSTR + c4 * 4) = hi;
    *(uint2*)(dl + ridx * KSTR + c4 * 4) = lo;
}
__global__ void convX_kernel(const float* __restrict__ x) {
    size_t idx = (size_t)blockIdx.x * 256 + threadIdx.x;   // T_TOK*1024
    split_store(x, g_xh, g_xl, idx >> 10, (int)(idx & 1023), D_IN);
}
__global__ void convW_kernel(const float* __restrict__ W) {
    size_t idx = (size_t)blockIdx.x * 256 + threadIdx.x;   // D_OUT*1024
    split_store(W, g_Wh, g_Wl, idx >> 10, (int)(idx & 1023), D_IN);
}

// ============================================================================
// Kernel 2: GEMM via mma.sync bf16 (HMMA), 3-term split (hh + hl + lh),
// 3-stage cp.async pipeline. CTA 128x128, KC=64, 8 warps of 64x32,
// 66 K-chunks over extended K (lora K appended).
// smem planes per stage: Ah | Al | Bh | Bl (16KB each, swizzled 128B rows).
// ============================================================================
#define NCH    66
#define PLANE  16384
#define STG_SZ (4 * PLANE)          // 64 KB
#define K2_SMEM (3 * STG_SZ)        // 192 KB

__device__ __forceinline__ void issue_stage(uint32_t sb, int s, int c,
                                            int m0, int n0, int tid) {
    uint32_t sbase = sb + s * STG_SZ;
    size_t koff = (size_t)c * 64;
#pragma unroll
    for (int t = 0; t < 4; ++t) {
        int idx = tid + t * 256;
        int row = idx >> 3, c8 = idx & 7;
        uint32_t so = (uint32_t)(row * 128 + ((c8 * 16) ^ ((row & 7) << 4)));
        cpasync16(sbase + 0 * PLANE + so, g_xh + (size_t)(m0 + row) * KSTR + koff + c8 * 8);
        cpasync16(sbase + 1 * PLANE + so, g_xl + (size_t)(m0 + row) * KSTR + koff + c8 * 8);
        cpasync16(sbase + 2 * PLANE + so, g_Wh + (size_t)(n0 + row) * KSTR + koff + c8 * 8);
        cpasync16(sbase + 3 * PLANE + so, g_Wl + (size_t)(n0 + row) * KSTR + koff + c8 * 8);
    }
    cp_commit();
}

__global__ void __launch_bounds__(256, 1) gemm_kernel(
    const float* __restrict__ bias, float* __restrict__ out)
{
    extern __shared__ char smc[];
    const uint32_t sb = smem_to_u32(smc);
    const int tid = threadIdx.x;
    const int lane = tid & 31;
    const int wid = tid >> 5;
    const int wm = wid >> 2;            // 0..1 -> m offset 64
    const int wn = wid & 3;             // 0..3 -> n offset 32
    const int n0 = blockIdx.x * 128;
    const int m0 = blockIdx.y * 128;

    const int jg = lane >> 3, rr = lane & 7;
    const uint32_t xorv = (uint32_t)(rr << 4);
    const uint32_t arow = (uint32_t)((jg & 1) * 8 + rr);
    const uint32_t akb  = (uint32_t)((jg >> 1) * 16);
    const uint32_t brow = (uint32_t)((jg >> 1) * 8 + rr);
    const uint32_t bkb  = (uint32_t)((jg & 1) * 16);

    float acc[4][4][4];
#pragma unroll
    for (int i = 0; i < 4; ++i)
#pragma unroll
        for (int j = 0; j < 4; ++j)
#pragma unroll
            for (int q = 0; q < 4; ++q) acc[i][j][q] = 0.0f;

    issue_stage(sb, 0, 0, m0, n0, tid);
    issue_stage(sb, 1, 1, m0, n0, tid);

#pragma unroll 1
    for (int c = 0; c < NCH; ++c) {
        const int s = c % 3;
        if (c == NCH - 1) asm volatile("cp.async.wait_group 0;" ::: "memory");
        else              asm volatile("cp.async.wait_group 1;" ::: "memory");
        __syncthreads();

        const uint32_t sA = sb + s * STG_SZ;
        const uint32_t sB = sA + 2 * PLANE;
#pragma unroll
        for (int k16 = 0; k16 < 4; ++k16) {
            const uint32_t kbA = ((uint32_t)(k16 * 32) + akb) ^ xorv;
            const uint32_t kbB = ((uint32_t)(k16 * 32) + bkb) ^ xorv;
            uint32_t ah[4][4], al[4][4], bh[8], bl[8];
#pragma unroll
            for (int i = 0; i < 4; ++i) {
                uint32_t ro = (uint32_t)((wm * 64 + i * 16 + arow) * 128);
                ldsm4(ah[i], sA + ro + kbA);
                ldsm4(al[i], sA + PLANE + ro + kbA);
            }
#pragma unroll
            for (int j2 = 0; j2 < 2; ++j2) {
                uint32_t ro = (uint32_t)((wn * 32 + j2 * 16 + brow) * 128);
                ldsm4(bh + j2 * 4, sB + ro + kbB);
                ldsm4(bl + j2 * 4, sB + PLANE + ro + kbB);
            }
            // hh
#pragma unroll
            for (int i = 0; i < 4; ++i)
#pragma unroll
                for (int j = 0; j < 4; ++j)
                    mma16816(acc[i][j], ah[i], &bh[j * 2]);
            // hl
#pragma unroll
            for (int i = 0; i < 4; ++i)
#pragma unroll
                for (int j = 0; j < 4; ++j)
                    mma16816(acc[i][j], ah[i], &bl[j * 2]);
            // lh
#pragma unroll
            for (int i = 0; i < 4; ++i)
#pragma unroll
                for (int j = 0; j < 4; ++j)
                    mma16816(acc[i][j], al[i], &bh[j * 2]);
        }
        if (c + 2 < NCH) issue_stage(sb, (c + 2) % 3, c + 2, m0, n0, tid);
    }

    // Epilogue: add bias, store fp32
    const int gi = lane >> 2;     // 0..7
    const int tg = lane & 3;      // 0..3
#pragma unroll
    for (int j = 0; j < 4; ++j) {
        const int ncol = n0 + wn * 32 + j * 8 + tg * 2;
        const float b0 = bias[ncol], b1 = bias[ncol + 1];
#pragma unroll
        for (int i = 0; i < 4; ++i) {
            const int r0 = m0 + wm * 64 + i * 16 + gi;
            float2 v0 = make_float2(acc[i][j][0] + b0, acc[i][j][1] + b1);
            float2 v1 = make_float2(acc[i][j][2] + b0, acc[i][j][3] + b1);
            *(float2*)(out + (size_t)r0 * D_OUT + ncol) = v0;
            *(float2*)(out + (size_t)(r0 + 8) * D_OUT + ncol) = v1;
        }
    }
}

// ============================================================================
// Launch
// ============================================================================
extern "C" void kernel_launch(void* const* d_in, const int* in_sizes, int n_in,
                              void* d_out, int out_size)
{
    const float* x      = (const float*)d_in[0];
    const float* W      = (const float*)d_in[1];
    const float* bias   = (const float*)d_in[2];
    const float* routeW = (const float*)d_in[3];
    const float* loraA  = (const float*)d_in[4];
    const float* loraB  = (const float*)d_in[5];
    float* out = (float*)d_out;

    const size_t RES = (size_t)T_TOK * D_OUT;
    float* out_rw;
    float* out_gs;
    if ((size_t)out_size >= RES + 2u * T_TOK * N_EXP) {
        out_rw = out + RES;
        out_gs = out_rw + (size_t)T_TOK * N_EXP;
    } else {
        float* dummy;
        cudaGetSymbolAddress((void**)&dummy, g_dummy_rw);
        out_rw = dummy;
        out_gs = dummy + (size_t)T_TOK * N_EXP;
    }

    cudaFuncSetAttribute(router_kernel, cudaFuncAttributeMaxDynamicSharedMemorySize, K1_SMEM_BYTES);
    cudaFuncSetAttribute(gemm_kernel,  cudaFuncAttributeMaxDynamicSharedMemorySize, K2_SMEM);

    router_kernel<<<T_TOK / K1_TOKS, 256, K1_SMEM_BYTES>>>(x, routeW, loraA, out_rw, out_gs);
    packL_kernel<<<(D_OUT * KEXTRA) / 256, 256>>>(loraB);
    convX_kernel<<<(T_TOK * (D_IN / 4)) / 256, 256>>>(x);
    convW_kernel<<<(D_OUT * (D_IN / 4)) / 256, 256>>>(W);
    gemm_kernel<<<dim3(D_OUT / 128, T_TOK / 128), 256, K2_SMEM>>>(bias, out);
}

// round 4
// speedup vs baseline: 1.0689x; 1.0689x over previous
#include <cuda_runtime.h>
#include <cuda_bf16.h>
#include <cstdint>

// ============================================================================
// Problem constants
// ============================================================================
#define T_TOK   8192        // B*S
#define D_IN    4096
#define D_OUT   4096
#define N_EXP   8
#define RANK    16
#define KEXTRA  128         // E*R
#define KSTR    4224        // D_IN + KEXTRA (extended K)
#define SCALING 2.0f

// ============================================================================
// Persistent device scratch (static arrays: allocation-free)
// ============================================================================
__device__ __nv_bfloat16 g_xh[(size_t)T_TOK * KSTR];
__device__ __nv_bfloat16 g_xl[(size_t)T_TOK * KSTR];
__device__ __nv_bfloat16 g_Wh[(size_t)D_OUT * KSTR];
__device__ __nv_bfloat16 g_Wl[(size_t)D_OUT * KSTR];
__device__ __nv_bfloat16 g_Ah[(size_t)KEXTRA * D_IN];   // lora_A hi plane
__device__ __nv_bfloat16 g_Al[(size_t)KEXTRA * D_IN];   // lora_A lo plane
__device__ float g_rw[(size_t)T_TOK * N_EXP];           // routing weights
__device__ float g_dummy_rw[2 * T_TOK * N_EXP];

// ============================================================================
// Helpers (sm_80-compatible PTX only; ptxas targets plain sm_103)
// ============================================================================
__device__ __forceinline__ uint32_t smem_to_u32(const void* p) {
    uint32_t a;
    asm("{ .reg .u64 t; cvta.to.shared.u64 t, %1; cvt.u32.u64 %0, t; }" : "=r"(a) : "l"(p));
    return a;
}
__device__ __forceinline__ void cpasync16(uint32_t saddr, const void* g) {
    asm volatile("cp.async.cg.shared.global [%0], [%1], 16;" :: "r"(saddr), "l"(g));
}
__device__ __forceinline__ void cp_commit() {
    asm volatile("cp.async.commit_group;" ::: "memory");
}
__device__ __forceinline__ void ldsm4(uint32_t* r, uint32_t addr) {
    asm volatile("ldmatrix.sync.aligned.m8n8.x4.shared.b16 {%0,%1,%2,%3}, [%4];"
                 : "=r"(r[0]), "=r"(r[1]), "=r"(r[2]), "=r"(r[3]) : "r"(addr));
}
__device__ __forceinline__ void mma16816(float* c, const uint32_t* a, const uint32_t* b) {
    asm volatile(
        "mma.sync.aligned.m16n8k16.row.col.f32.bf16.bf16.f32 "
        "{%0,%1,%2,%3}, {%4,%5,%6,%7}, {%8,%9}, {%0,%1,%2,%3};"
        : "+f"(c[0]), "+f"(c[1]), "+f"(c[2]), "+f"(c[3])
        : "r"(a[0]), "r"(a[1]), "r"(a[2]), "r"(a[3]), "r"(b[0]), "r"(b[1]));
}
__device__ __forceinline__ uint32_t pack_bf16(float a, float b) {
    __nv_bfloat16 ha = __float2bfloat16_rn(a);
    __nv_bfloat16 hb = __float2bfloat16_rn(b);
    return (uint32_t)__bfloat16_as_ushort(ha) | ((uint32_t)__bfloat16_as_ushort(hb) << 16);
}

// ============================================================================
// Kernel: gate (fp32) — gate_score, softmax, top-2, renorm. 64 tokens/block.
// ============================================================================
#define GT_XS 0                      // xsT[64k][65t]
#define GT_WS (64 * 65)              // ws[8][68]
#define GT_GS (GT_WS + 8 * 68)       // gs[64][9]
#define GT_FLOATS (GT_GS + 64 * 9)
#define GT_SMEM (GT_FLOATS * 4)

__global__ void __launch_bounds__(256) gate_kernel(
    const float* __restrict__ x, const float* __restrict__ routeW,
    float* __restrict__ out_rw, float* __restrict__ out_gs)
{
    extern __shared__ float sm[];
    float* xsT = sm + GT_XS;
    float* ws  = sm + GT_WS;
    float* gs  = sm + GT_GS;

    const int tid = threadIdx.x;
    const int tok0 = blockIdx.x * 64;
    const int t  = tid >> 2;
    const int eq = tid & 3;

    float a0 = 0.0f, a1 = 0.0f;
    for (int kb = 0; kb < D_IN / 64; ++kb) {
#pragma unroll
        for (int i = 0; i < 4; ++i) {
            int f = tid + 256 * i;
            int tr = f >> 4, c4 = f & 15;
            float4 v = *(const float4*)(x + (size_t)(tok0 + tr) * D_IN + kb * 64 + c4 * 4);
            int k0 = c4 * 4;
            xsT[(k0 + 0) * 65 + tr] = v.x;
            xsT[(k0 + 1) * 65 + tr] = v.y;
            xsT[(k0 + 2) * 65 + tr] = v.z;
            xsT[(k0 + 3) * 65 + tr] = v.w;
        }
        if (tid < 128) {
            int j = tid >> 4, c4 = tid & 15;
            float4 v = *(const float4*)(routeW + (size_t)j * D_IN + kb * 64 + c4 * 4);
            *(float4*)(ws + j * 68 + c4 * 4) = v;
        }
        __syncthreads();
#pragma unroll 8
        for (int k = 0; k < 64; ++k) {
            float xv = xsT[k * 65 + t];
            a0 = fmaf(xv, ws[eq * 68 + k], a0);
            a1 = fmaf(xv, ws[(eq + 4) * 68 + k], a1);
        }
        __syncthreads();
    }
    gs[t * 9 + eq] = a0;
    gs[t * 9 + eq + 4] = a1;
    __syncthreads();

    if (tid < 64) {
        float g[N_EXP], m = -1e30f;
#pragma unroll
        for (int j = 0; j < N_EXP; ++j) { g[j] = gs[tid * 9 + j]; m = fmaxf(m, g[j]); }
        float p[N_EXP], s = 0.0f;
#pragma unroll
        for (int j = 0; j < N_EXP; ++j) { p[j] = expf(g[j] - m); s += p[j]; }
        float inv = 1.0f / s;
#pragma unroll
        for (int j = 0; j < N_EXP; ++j) p[j] *= inv;

        int i1 = 0;
#pragma unroll
        for (int j = 1; j < N_EXP; ++j) if (p[j] > p[i1]) i1 = j;
        int i2 = (i1 == 0) ? 1 : 0;
#pragma unroll
        for (int j = 0; j < N_EXP; ++j) if (j != i1 && p[j] > p[i2]) i2 = j;

        float denom = p[i1] + p[i2] + 1e-9f;
        float w1 = p[i1] / denom, w2 = p[i2] / denom;

        size_t ob = (size_t)(tok0 + tid) * N_EXP;
#pragma unroll
        for (int j = 0; j < N_EXP; ++j) {
            out_gs[ob + j] = g[j];
            float w = (j == i1) ? w1 : ((j == i2) ? w2 : 0.0f);
            out_rw[ob + j] = w;
            g_rw[ob + j] = w;
        }
    }
}

// ============================================================================
// Split-convert kernels: fp32 -> bf16 hi/lo planes
// ============================================================================
__device__ __forceinline__ void split_store(const float* src, __nv_bfloat16* dh,
                                            __nv_bfloat16* dl, size_t ridx, int c4,
                                            int src_stride, int dst_stride) {
    float4 v = *(const float4*)(src + ridx * src_stride + c4 * 4);
    __nv_bfloat16 h0 = __float2bfloat16_rn(v.x);
    __nv_bfloat16 h1 = __float2bfloat16_rn(v.y);
    __nv_bfloat16 h2 = __float2bfloat16_rn(v.z);
    __nv_bfloat16 h3 = __float2bfloat16_rn(v.w);
    uint2 hi, lo;
    hi.x = (uint32_t)__bfloat16_as_ushort(h0) | ((uint32_t)__bfloat16_as_ushort(h1) << 16);
    hi.y = (uint32_t)__bfloat16_as_ushort(h2) | ((uint32_t)__bfloat16_as_ushort(h3) << 16);
    lo.x = pack_bf16(v.x - __bfloat162float(h0), v.y - __bfloat162float(h1));
    lo.y = pack_bf16(v.z - __bfloat162float(h2), v.w - __bfloat162float(h3));
    *(uint2*)(dh + ridx * dst_stride + c4 * 4) = hi;
    *(uint2*)(dl + ridx * dst_stride + c4 * 4) = lo;
}
__global__ void convX_kernel(const float* __restrict__ x) {
    size_t idx = (size_t)blockIdx.x * 256 + threadIdx.x;   // T_TOK*1024
    split_store(x, g_xh, g_xl, idx >> 10, (int)(idx & 1023), D_IN, KSTR);
}
__global__ void convW_kernel(const float* __restrict__ W) {
    size_t idx = (size_t)blockIdx.x * 256 + threadIdx.x;   // D_OUT*1024
    split_store(W, g_Wh, g_Wl, idx >> 10, (int)(idx & 1023), D_IN, KSTR);
}
__global__ void convA_kernel(const float* __restrict__ loraA) {
    size_t idx = (size_t)blockIdx.x * 256 + threadIdx.x;   // KEXTRA*1024
    split_store(loraA, g_Ah, g_Al, idx >> 10, (int)(idx & 1023), D_IN, D_IN);
}
__global__ void packL_kernel(const float* __restrict__ loraB) {
    int idx = blockIdx.x * 256 + threadIdx.x;   // D_OUT*KEXTRA
    int o = idx >> 7, kk = idx & 127;
    int e = kk >> 4, r = kk & 15;
    float val = loraB[((size_t)e * D_OUT + o) * RANK + r];
    __nv_bfloat16 hi = __float2bfloat16_rn(val);
    size_t p = (size_t)o * KSTR + D_IN + kk;
    g_Wh[p] = hi;
    g_Wl[p] = __float2bfloat16_rn(val - __bfloat162float(hi));
}

// ============================================================================
// Kernel: hgemm — h = x * lora_A^T [T_TOK x 128], 3-term bf16 HMMA.
// Epilogue: g = SCALING * rw[t, col>>4] * h, split to bf16, write to lora
// columns of g_xh/g_xl. Tile 64x128, 8 warps (2x4), 2-stage cp.async.
// ============================================================================
#define H_PA 8192
#define H_PB 16384
#define H_STG (2 * H_PA + 2 * H_PB)    // 49152
#define H_SMEM (2 * H_STG)             // 98304
#define H_NCH (D_IN / 64)              // 64

__device__ __forceinline__ void h_issue(uint32_t sb, int s, int c, int m0, int tid) {
    uint32_t sbase = sb + s * H_STG;
    size_t koff = (size_t)c * 64;
#pragma unroll
    for (int t = 0; t < 4; ++t) {                       // A: 2 planes * 64*8
        int idx = tid + 256 * t;
        int plane = idx >> 9, rem = idx & 511;
        int row = rem >> 3, c8 = rem & 7;
        uint32_t so = (uint32_t)(row * 128 + ((c8 * 16) ^ ((row & 7) << 4)));
        const __nv_bfloat16* src = (plane ? g_xl : g_xh) + (size_t)(m0 + row) * KSTR + koff + c8 * 8;
        cpasync16(sbase + plane * H_PA + so, src);
    }
#pragma unroll
    for (int t = 0; t < 8; ++t) {                       // B: 2 planes * 128*8
        int idx = tid + 256 * t;
        int plane = idx >> 10, rem = idx & 1023;
        int row = rem >> 3, c8 = rem & 7;
        uint32_t so = (uint32_t)(row * 128 + ((c8 * 16) ^ ((row & 7) << 4)));
        const __nv_bfloat16* src = (plane ? g_Al : g_Ah) + (size_t)row * D_IN + koff + c8 * 8;
        cpasync16(sbase + 2 * H_PA + plane * H_PB + so, src);
    }
    cp_commit();
}

__global__ void __launch_bounds__(256, 1) hgemm_kernel() {
    extern __shared__ char smc[];
    const uint32_t sb = smem_to_u32(smc);
    const int tid = threadIdx.x;
    const int lane = tid & 31;
    const int wid = tid >> 5;
    const int wm = wid >> 2;        // 0..1
    const int wn = wid & 3;         // 0..3
    const int m0 = blockIdx.x * 64;

    const int jg = lane >> 3, rr = lane & 7;
    const uint32_t xorv = (uint32_t)(rr << 4);
    const uint32_t arow = (uint32_t)((jg & 1) * 8 + rr);
    const uint32_t akb  = (uint32_t)((jg >> 1) * 16);
    const uint32_t brow = (uint32_t)((jg >> 1) * 8 + rr);
    const uint32_t bkb  = (uint32_t)((jg & 1) * 16);

    float acc[2][4][4];
#pragma unroll
    for (int i = 0; i < 2; ++i)
#pragma unroll
        for (int j = 0; j < 4; ++j)
#pragma unroll
            for (int q = 0; q < 4; ++q) acc[i][j][q] = 0.0f;

    h_issue(sb, 0, 0, m0, tid);

#pragma unroll 1
    for (int c = 0; c < H_NCH; ++c) {
        const int s = c & 1;
        if (c + 1 < H_NCH) h_issue(sb, s ^ 1, c + 1, m0, tid);
        if (c + 1 < H_NCH) asm volatile("cp.async.wait_group 1;" ::: "memory");
        else               asm volatile("cp.async.wait_group 0;" ::: "memory");
        __syncthreads();

        const uint32_t sA  = sb + s * H_STG;
        const uint32_t sAl = sA + H_PA;
        const uint32_t sB  = sA + 2 * H_PA;
        const uint32_t sBl = sB + H_PB;
#pragma unroll
        for (int k16 = 0; k16 < 4; ++k16) {
            const uint32_t kA = ((uint32_t)(k16 * 32) + akb) ^ xorv;
            const uint32_t kB = ((uint32_t)(k16 * 32) + bkb) ^ xorv;
            uint32_t ah[2][4], al[2][4];
#pragma unroll
            for (int i = 0; i < 2; ++i) {
                uint32_t ro = (uint32_t)((wm * 32 + i * 16 + arow) * 128);
                ldsm4(ah[i], sA + ro + kA);
                ldsm4(al[i], sAl + ro + kA);
            }
#pragma unroll
            for (int j2 = 0; j2 < 2; ++j2) {
                uint32_t bh[4], bl[4];
                uint32_t ro = (uint32_t)((wn * 32 + j2 * 16 + brow) * 128);
                ldsm4(bh, sB + ro + kB);
                ldsm4(bl, sBl + ro + kB);
#pragma unroll
                for (int i = 0; i < 2; ++i) {
                    mma16816(acc[i][j2 * 2],     ah[i], bh);
                    mma16816(acc[i][j2 * 2 + 1], ah[i], bh + 2);
                    mma16816(acc[i][j2 * 2],     ah[i], bl);
                    mma16816(acc[i][j2 * 2 + 1], ah[i], bl + 2);
                    mma16816(acc[i][j2 * 2],     al[i], bh);
                    mma16816(acc[i][j2 * 2 + 1], al[i], bh + 2);
                }
            }
        }
        __syncthreads();
    }

    // Epilogue: gate/scale/split, write lora columns of g_xh/g_xl
    const int gi = lane >> 2;
    const int tg = lane & 3;
#pragma unroll
    for (int i = 0; i < 2; ++i)
#pragma unroll
        for (int j = 0; j < 4; ++j) {
            int col = wn * 32 + j * 8 + tg * 2;
            int e = col >> 4;
#pragma unroll
            for (int half = 0; half < 2; ++half) {
                int r = m0 + wm * 32 + i * 16 + gi + half * 8;
                float rw = SCALING * g_rw[(size_t)r * N_EXP + e];
                float v0 = acc[i][j][half * 2 + 0] * rw;
                float v1 = acc[i][j][half * 2 + 1] * rw;
                __nv_bfloat16 h0 = __float2bfloat16_rn(v0);
                __nv_bfloat16 h1 = __float2bfloat16_rn(v1);
                size_t o = (size_t)r * KSTR + D_IN + col;
                g_xh[o] = h0;
                g_xh[o + 1] = h1;
                g_xl[o] = __float2bfloat16_rn(v0 - __bfloat162float(h0));
                g_xl[o + 1] = __float2bfloat16_rn(v1 - __bfloat162float(h1));
            }
        }
}

// ============================================================================
// Kernel: main GEMM — out = bias + Xext * Wext^T over extended K (lora fused).
// 3-term bf16 HMMA. Tile 128x256xKC64, 16 warps (4x4, warp 32x64), 2-stage.
// ============================================================================
#define M_PA 16384
#define M_PB 32768
#define M_STG (2 * M_PA + 2 * M_PB)    // 98304
#define M_SMEM (2 * M_STG)             // 196608
#define M_NCH (KSTR / 64)              // 66

__device__ __forceinline__ void m_issue(uint32_t sb, int s, int c, int m0, int n0, int tid) {
    uint32_t sbase = sb + s * M_STG;
    size_t koff = (size_t)c * 64;
#pragma unroll
    for (int t = 0; t < 4; ++t) {                       // A: 2 planes * 128*8
        int idx = tid + 512 * t;
        int plane = idx >> 10, rem = idx & 1023;
        int row = rem >> 3, c8 = rem & 7;
        uint32_t so = (uint32_t)(row * 128 + ((c8 * 16) ^ ((row & 7) << 4)));
        const __nv_bfloat16* src = (plane ? g_xl : g_xh) + (size_t)(m0 + row) * KSTR + koff + c8 * 8;
        cpasync16(sbase + plane * M_PA + so, src);
    }
#pragma unroll
    for (int t = 0; t < 8; ++t) {                       // B: 2 planes * 256*8
        int idx = tid + 512 * t;
        int plane = idx >> 11, rem = idx & 2047;
        int row = rem >> 3, c8 = rem & 7;
        uint32_t so = (uint32_t)(row * 128 + ((c8 * 16) ^ ((row & 7) << 4)));
        const __nv_bfloat16* src = (plane ? g_Wl : g_Wh) + (size_t)(n0 + row) * KSTR + koff + c8 * 8;
        cpasync16(sbase + 2 * M_PA + plane * M_PB + so, src);
    }
    cp_commit();
}

__global__ void __launch_bounds__(512, 1) gemm_kernel(
    const float* __restrict__ bias, float* __restrict__ out)
{
    extern __shared__ char smc[];
    const uint32_t sb = smem_to_u32(smc);
    const int tid = threadIdx.x;
    const int lane = tid & 31;
    const int wid = tid >> 5;
    const int wm = wid >> 2;        // 0..3 -> m offset *32
    const int wn = wid & 3;         // 0..3 -> n offset *64
    const int n0 = blockIdx.x * 256;
    const int m0 = blockIdx.y * 128;

    const int jg = lane >> 3, rr = lane & 7;
    const uint32_t xorv = (uint32_t)(rr << 4);
    const uint32_t arow = (uint32_t)((jg & 1) * 8 + rr);
    const uint32_t akb  = (uint32_t)((jg >> 1) * 16);
    const uint32_t brow = (uint32_t)((jg >> 1) * 8 + rr);
    const uint32_t bkb  = (uint32_t)((jg & 1) * 16);

    float acc[2][8][4];
#pragma unroll
    for (int i = 0; i < 2; ++i)
#pragma unroll
        for (int j = 0; j < 8; ++j)
#pragma unroll
            for (int q = 0; q < 4; ++q) acc[i][j][q] = 0.0f;

    m_issue(sb, 0, 0, m0, n0, tid);

#pragma unroll 1
    for (int c = 0; c < M_NCH; ++c) {
        const int s = c & 1;
        if (c + 1 < M_NCH) m_issue(sb, s ^ 1, c + 1, m0, n0, tid);
        if (c + 1 < M_NCH) asm volatile("cp.async.wait_group 1;" ::: "memory");
        else               asm volatile("cp.async.wait_group 0;" ::: "memory");
        __syncthreads();

        const uint32_t sA  = sb + s * M_STG;
        const uint32_t sAl = sA + M_PA;
        const uint32_t sB  = sA + 2 * M_PA;
        const uint32_t sBl = sB + M_PB;
#pragma unroll
        for (int k16 = 0; k16 < 4; ++k16) {
            const uint32_t kA = ((uint32_t)(k16 * 32) + akb) ^ xorv;
            const uint32_t kB = ((uint32_t)(k16 * 32) + bkb) ^ xorv;
            uint32_t ah[2][4], al[2][4];
#pragma unroll
            for (int i = 0; i < 2; ++i) {
                uint32_t ro = (uint32_t)((wm * 32 + i * 16 + arow) * 128);
                ldsm4(ah[i], sA + ro + kA);
                ldsm4(al[i], sAl + ro + kA);
            }
#pragma unroll
            for (int j2 = 0; j2 < 4; ++j2) {
                uint32_t bh[4], bl[4];
                uint32_t ro = (uint32_t)((wn * 64 + j2 * 16 + brow) * 128);
                ldsm4(bh, sB + ro + kB);
                ldsm4(bl, sBl + ro + kB);
#pragma unroll
                for (int i = 0; i < 2; ++i) {
                    mma16816(acc[i][j2 * 2],     ah[i], bh);
                    mma16816(acc[i][j2 * 2 + 1], ah[i], bh + 2);
                    mma16816(acc[i][j2 * 2],     ah[i], bl);
                    mma16816(acc[i][j2 * 2 + 1], ah[i], bl + 2);
                    mma16816(acc[i][j2 * 2],     al[i], bh);
                    mma16816(acc[i][j2 * 2 + 1], al[i], bh + 2);
                }
            }
        }
        __syncthreads();
    }

    // Epilogue: bias + fp32 store
    const int gi = lane >> 2;
    const int tg = lane & 3;
#pragma unroll
    for (int j = 0; j < 8; ++j) {
        const int ncol = n0 + wn * 64 + j * 8 + tg * 2;
        const float b0 = bias[ncol], b1 = bias[ncol + 1];
#pragma unroll
        for (int i = 0; i < 2; ++i) {
            const int r0 = m0 + wm * 32 + i * 16 + gi;
            float2 v0 = make_float2(acc[i][j][0] + b0, acc[i][j][1] + b1);
            float2 v1 = make_float2(acc[i][j][2] + b0, acc[i][j][3] + b1);
            *(float2*)(out + (size_t)r0 * D_OUT + ncol) = v0;
            *(float2*)(out + (size_t)(r0 + 8) * D_OUT + ncol) = v1;
        }
    }
}

// ============================================================================
// Launch
// ============================================================================
extern "C" void kernel_launch(void* const* d_in, const int* in_sizes, int n_in,
                              void* d_out, int out_size)
{
    const float* x      = (const float*)d_in[0];
    const float* W      = (const float*)d_in[1];
    const float* bias   = (const float*)d_in[2];
    const float* routeW = (const float*)d_in[3];
    const float* loraA  = (const float*)d_in[4];
    const float* loraB  = (const float*)d_in[5];
    float* out = (float*)d_out;

    const size_t RES = (size_t)T_TOK * D_OUT;
    float* out_rw;
    float* out_gs;
    if ((size_t)out_size >= RES + 2u * T_TOK * N_EXP) {
        out_rw = out + RES;
        out_gs = out_rw + (size_t)T_TOK * N_EXP;
    } else {
        float* dummy;
        cudaGetSymbolAddress((void**)&dummy, g_dummy_rw);
        out_rw = dummy;
        out_gs = dummy + (size_t)T_TOK * N_EXP;
    }

    cudaFuncSetAttribute(gate_kernel,  cudaFuncAttributeMaxDynamicSharedMemorySize, GT_SMEM);
    cudaFuncSetAttribute(hgemm_kernel, cudaFuncAttributeMaxDynamicSharedMemorySize, H_SMEM);
    cudaFuncSetAttribute(gemm_kernel,  cudaFuncAttributeMaxDynamicSharedMemorySize, M_SMEM);

    gate_kernel<<<T_TOK / 64, 256, GT_SMEM>>>(x, routeW, out_rw, out_gs);
    convX_kernel<<<(T_TOK * (D_IN / 4)) / 256, 256>>>(x);
    convW_kernel<<<(D_OUT * (D_IN / 4)) / 256, 256>>>(W);
    convA_kernel<<<(KEXTRA * (D_IN / 4)) / 256, 256>>>(loraA);
    packL_kernel<<<(D_OUT * KEXTRA) / 256, 256>>>(loraB);
    hgemm_kernel<<<T_TOK / 64, 256, H_SMEM>>>();
    gemm_kernel<<<dim3(D_OUT / 256, T_TOK / 128), 512, M_SMEM>>>(bias, out);
}

// round 8
// speedup vs baseline: 2.4664x; 2.3074x over previous
#include <cuda_runtime.h>
#include <cuda_bf16.h>
#include <cuda_fp16.h>
#include <cstdint>

// ============================================================================
// Problem constants
// ============================================================================
#define T_TOK   8192        // B*S
#define D_IN    4096
#define D_OUT   4096
#define N_EXP   8
#define RANK    16
#define KEXTRA  128         // E*R
#define KSTR    4224        // D_IN + KEXTRA (extended K)
#define SCALING 2.0f

// ============================================================================
// Persistent device scratch (static arrays: allocation-free)
// Single fp16 plane per matrix (1-pass HMMA; fp16 mantissa gives ~4e-4 norm err)
// ============================================================================
__device__ __half g_x16[(size_t)T_TOK * KSTR];    // 69.2 MB
__device__ __half g_W16[(size_t)D_OUT * KSTR];    // 34.6 MB
__device__ __half g_A16[(size_t)KEXTRA * D_IN];   // 1 MB
__device__ float  g_rw[(size_t)T_TOK * N_EXP];
__device__ float  g_dummy_rw[2 * T_TOK * N_EXP];

// ============================================================================
// Helpers (sm_80-compatible PTX only; ptxas targets plain sm_103)
// ============================================================================
__device__ __forceinline__ uint32_t smem_to_u32(const void* p) {
    uint32_t a;
    asm("{ .reg .u64 t; cvta.to.shared.u64 t, %1; cvt.u32.u64 %0, t; }" : "=r"(a) : "l"(p));
    return a;
}
__device__ __forceinline__ void cpasync16(uint32_t saddr, const void* g) {
    asm volatile("cp.async.cg.shared.global [%0], [%1], 16;" :: "r"(saddr), "l"(g));
}
__device__ __forceinline__ void cp_commit() {
    asm volatile("cp.async.commit_group;" ::: "memory");
}
__device__ __forceinline__ void ldsm4(uint32_t* r, uint32_t addr) {
    asm volatile("ldmatrix.sync.aligned.m8n8.x4.shared.b16 {%0,%1,%2,%3}, [%4];"
                 : "=r"(r[0]), "=r"(r[1]), "=r"(r[2]), "=r"(r[3]) : "r"(addr));
}
__device__ __forceinline__ void mma16816(float* c, const uint32_t* a, const uint32_t* b) {
    asm volatile(
        "mma.sync.aligned.m16n8k16.row.col.f32.f16.f16.f32 "
        "{%0,%1,%2,%3}, {%4,%5,%6,%7}, {%8,%9}, {%0,%1,%2,%3};"
        : "+f"(c[0]), "+f"(c[1]), "+f"(c[2]), "+f"(c[3])
        : "r"(a[0]), "r"(a[1]), "r"(a[2]), "r"(a[3]), "r"(b[0]), "r"(b[1]));
}

// ============================================================================
// Kernel: gate (fp32) — gate_score, softmax, top-2, renorm. 64 tokens/block.
// ============================================================================
#define GT_XS 0
#define GT_WS (64 * 65)
#define GT_GS (GT_WS + 8 * 68)
#define GT_FLOATS (GT_GS + 64 * 9)
#define GT_SMEM (GT_FLOATS * 4)

__global__ void __launch_bounds__(256) gate_kernel(
    const float* __restrict__ x, const float* __restrict__ routeW,
    float* __restrict__ out_rw, float* __restrict__ out_gs)
{
    extern __shared__ float sm[];
    float* xsT = sm + GT_XS;
    float* ws  = sm + GT_WS;
    float* gs  = sm + GT_GS;

    const int tid = threadIdx.x;
    const int tok0 = blockIdx.x * 64;
    const int t  = tid >> 2;
    const int eq = tid & 3;

    float a0 = 0.0f, a1 = 0.0f;
    for (int kb = 0; kb < D_IN / 64; ++kb) {
#pragma unroll
        for (int i = 0; i < 4; ++i) {
            int f = tid + 256 * i;
            int tr = f >> 4, c4 = f & 15;
            float4 v = *(const float4*)(x + (size_t)(tok0 + tr) * D_IN + kb * 64 + c4 * 4);
            int k0 = c4 * 4;
            xsT[(k0 + 0) * 65 + tr] = v.x;
            xsT[(k0 + 1) * 65 + tr] = v.y;
            xsT[(k0 + 2) * 65 + tr] = v.z;
            xsT[(k0 + 3) * 65 + tr] = v.w;
        }
        if (tid < 128) {
            int j = tid >> 4, c4 = tid & 15;
            float4 v = *(const float4*)(routeW + (size_t)j * D_IN + kb * 64 + c4 * 4);
            *(float4*)(ws + j * 68 + c4 * 4) = v;
        }
        __syncthreads();
#pragma unroll 8
        for (int k = 0; k < 64; ++k) {
            float xv = xsT[k * 65 + t];
            a0 = fmaf(xv, ws[eq * 68 + k], a0);
            a1 = fmaf(xv, ws[(eq + 4) * 68 + k], a1);
        }
        __syncthreads();
    }
    gs[t * 9 + eq] = a0;
    gs[t * 9 + eq + 4] = a1;
    __syncthreads();

    if (tid < 64) {
        float g[N_EXP], m = -1e30f;
#pragma unroll
        for (int j = 0; j < N_EXP; ++j) { g[j] = gs[tid * 9 + j]; m = fmaxf(m, g[j]); }
        float p[N_EXP], s = 0.0f;
#pragma unroll
        for (int j = 0; j < N_EXP; ++j) { p[j] = expf(g[j] - m); s += p[j]; }
        float inv = 1.0f / s;
#pragma unroll
        for (int j = 0; j < N_EXP; ++j) p[j] *= inv;

        int i1 = 0;
#pragma unroll
        for (int j = 1; j < N_EXP; ++j) if (p[j] > p[i1]) i1 = j;
        int i2 = (i1 == 0) ? 1 : 0;
#pragma unroll
        for (int j = 0; j < N_EXP; ++j) if (j != i1 && p[j] > p[i2]) i2 = j;

        float denom = p[i1] + p[i2] + 1e-9f;
        float w1 = p[i1] / denom, w2 = p[i2] / denom;

        size_t ob = (size_t)(tok0 + tid) * N_EXP;
#pragma unroll
        for (int j = 0; j < N_EXP; ++j) {
            out_gs[ob + j] = g[j];
            float w = (j == i1) ? w1 : ((j == i2) ? w2 : 0.0f);
            out_rw[ob + j] = w;
            g_rw[ob + j] = w;
        }
    }
}

// ============================================================================
// Convert kernels: fp32 -> fp16
// ============================================================================
__device__ __forceinline__ void conv_store(const float* src, __half* dst,
                                           size_t ridx, int c4,
                                           int src_stride, int dst_stride) {
    float4 v = *(const float4*)(src + ridx * src_stride + c4 * 4);
    __half2 h0 = __floats2half2_rn(v.x, v.y);
    __half2 h1 = __floats2half2_rn(v.z, v.w);
    uint2 o;
    o.x = *(uint32_t*)&h0;
    o.y = *(uint32_t*)&h1;
    *(uint2*)(dst + ridx * dst_stride + c4 * 4) = o;
}
__global__ void convX_kernel(const float* __restrict__ x) {
    size_t idx = (size_t)blockIdx.x * 256 + threadIdx.x;   // T_TOK*1024
    conv_store(x, g_x16, idx >> 10, (int)(idx & 1023), D_IN, KSTR);
}
__global__ void convW_kernel(const float* __restrict__ W) {
    size_t idx = (size_t)blockIdx.x * 256 + threadIdx.x;   // D_OUT*1024
    conv_store(W, g_W16, idx >> 10, (int)(idx & 1023), D_IN, KSTR);
}
__global__ void convA_kernel(const float* __restrict__ loraA) {
    size_t idx = (size_t)blockIdx.x * 256 + threadIdx.x;   // KEXTRA*1024
    conv_store(loraA, g_A16, idx >> 10, (int)(idx & 1023), D_IN, D_IN);
}
__global__ void packL_kernel(const float* __restrict__ loraB) {
    int idx = blockIdx.x * 256 + threadIdx.x;   // D_OUT*KEXTRA
    int o = idx >> 7, kk = idx & 127;
    int e = kk >> 4, r = kk & 15;
    g_W16[(size_t)o * KSTR + D_IN + kk] =
        __float2half_rn(loraB[((size_t)e * D_OUT + o) * RANK + r]);
}

// ============================================================================
// Kernel: hgemm — h = x * lora_A^T [T_TOK x 128], 1-pass fp16 HMMA.
// Epilogue: g = SCALING * rw[t, col>>4] * h -> fp16 lora columns of g_x16.
// Tile 64x128, 8 warps (2x4), 2-stage cp.async.
// ============================================================================
#define H_PA 8192
#define H_PB 16384
#define H_STG (H_PA + H_PB)            // 24576
#define H_SMEM (2 * H_STG)             // 49152
#define H_NCH (D_IN / 64)              // 64

__device__ __forceinline__ void h_issue(uint32_t sb, int s, int c, int m0, int tid) {
    uint32_t sbase = sb + s * H_STG;
    size_t koff = (size_t)c * 64;
#pragma unroll
    for (int t = 0; t < 2; ++t) {                       // A: 64 rows * 8
        int idx = tid + 256 * t;
        int row = idx >> 3, c8 = idx & 7;
        uint32_t so = (uint32_t)(row * 128 + ((c8 * 16) ^ ((row & 7) << 4)));
        cpasync16(sbase + so, g_x16 + (size_t)(m0 + row) * KSTR + koff + c8 * 8);
    }
#pragma unroll
    for (int t = 0; t < 4; ++t) {                       // B: 128 rows * 8
        int idx = tid + 256 * t;
        int row = idx >> 3, c8 = idx & 7;
        uint32_t so = (uint32_t)(row * 128 + ((c8 * 16) ^ ((row & 7) << 4)));
        cpasync16(sbase + H_PA + so, g_A16 + (size_t)row * D_IN + koff + c8 * 8);
    }
    cp_commit();
}

__global__ void __launch_bounds__(256, 1) hgemm_kernel() {
    extern __shared__ char smc[];
    const uint32_t sb = smem_to_u32(smc);
    const int tid = threadIdx.x;
    const int lane = tid & 31;
    const int wid = tid >> 5;
    const int wm = wid >> 2;        // 0..1
    const int wn = wid & 3;         // 0..3
    const int m0 = blockIdx.x * 64;

    const int jg = lane >> 3, rr = lane & 7;
    const uint32_t xorv = (uint32_t)(rr << 4);
    const uint32_t arow = (uint32_t)((jg & 1) * 8 + rr);
    const uint32_t akb  = (uint32_t)((jg >> 1) * 16);
    const uint32_t brow = (uint32_t)((jg >> 1) * 8 + rr);
    const uint32_t bkb  = (uint32_t)((jg & 1) * 16);

    float acc[2][4][4];
#pragma unroll
    for (int i = 0; i < 2; ++i)
#pragma unroll
        for (int j = 0; j < 4; ++j)
#pragma unroll
            for (int q = 0; q < 4; ++q) acc[i][j][q] = 0.0f;

    h_issue(sb, 0, 0, m0, tid);

#pragma unroll 1
    for (int c = 0; c < H_NCH; ++c) {
        const int s = c & 1;
        if (c + 1 < H_NCH) h_issue(sb, s ^ 1, c + 1, m0, tid);
        if (c + 1 < H_NCH) asm volatile("cp.async.wait_group 1;" ::: "memory");
        else               asm volatile("cp.async.wait_group 0;" ::: "memory");
        __syncthreads();

        const uint32_t sA = sb + s * H_STG;
        const uint32_t sB = sA + H_PA;
#pragma unroll
        for (int k16 = 0; k16 < 4; ++k16) {
            const uint32_t kA = ((uint32_t)(k16 * 32) + akb) ^ xorv;
            const uint32_t kB = ((uint32_t)(k16 * 32) + bkb) ^ xorv;
            uint32_t ah[2][4];
#pragma unroll
            for (int i = 0; i < 2; ++i) {
                uint32_t ro = (uint32_t)((wm * 32 + i * 16 + arow) * 128);
                ldsm4(ah[i], sA + ro + kA);
            }
#pragma unroll
            for (int j2 = 0; j2 < 2; ++j2) {
                uint32_t bh[4];
                uint32_t ro = (uint32_t)((wn * 32 + j2 * 16 + brow) * 128);
                ldsm4(bh, sB + ro + kB);
#pragma unroll
                for (int i = 0; i < 2; ++i) {
                    mma16816(acc[i][j2 * 2],     ah[i], bh);
                    mma16816(acc[i][j2 * 2 + 1], ah[i], bh + 2);
                }
            }
        }
        __syncthreads();
    }

    // Epilogue: gate/scale, write fp16 lora columns of g_x16
    const int gi = lane >> 2;
    const int tg = lane & 3;
#pragma unroll
    for (int i = 0; i < 2; ++i)
#pragma unroll
        for (int j = 0; j < 4; ++j) {
            int col = wn * 32 + j * 8 + tg * 2;
            int e = col >> 4;
#pragma unroll
            for (int half = 0; half < 2; ++half) {
                int r = m0 + wm * 32 + i * 16 + gi + half * 8;
                float rw = SCALING * g_rw[(size_t)r * N_EXP + e];
                __half2 hv = __floats2half2_rn(acc[i][j][half * 2 + 0] * rw,
                                               acc[i][j][half * 2 + 1] * rw);
                *(__half2*)(g_x16 + (size_t)r * KSTR + D_IN + col) = hv;
            }
        }
}

// ============================================================================
// Kernel: main GEMM — out = bias + Xext * Wext^T over extended K (lora fused).
// 1-pass fp16 HMMA. Tile 128x256xKC64, 16 warps (4x4, warp 32x64), 4-stage.
// ============================================================================
#define G_PA 16384
#define G_PB 32768
#define G_STG (G_PA + G_PB)            // 49152
#define G_SMEM (4 * G_STG)             // 196608
#define G_NCH (KSTR / 64)              // 66

__device__ __forceinline__ void m_issue(uint32_t sb, int s, int c, int m0, int n0, int tid) {
    uint32_t sbase = sb + s * G_STG;
    size_t koff = (size_t)c * 64;
#pragma unroll
    for (int t = 0; t < 2; ++t) {                       // A: 128 rows * 8
        int idx = tid + 512 * t;
        int row = idx >> 3, c8 = idx & 7;
        uint32_t so = (uint32_t)(row * 128 + ((c8 * 16) ^ ((row & 7) << 4)));
        cpasync16(sbase + so, g_x16 + (size_t)(m0 + row) * KSTR + koff + c8 * 8);
    }
#pragma unroll
    for (int t = 0; t < 4; ++t) {                       // B: 256 rows * 8
        int idx = tid + 512 * t;
        int row = idx >> 3, c8 = idx & 7;
        uint32_t so = (uint32_t)(row * 128 + ((c8 * 16) ^ ((row & 7) << 4)));
        cpasync16(sbase + G_PA + so, g_W16 + (size_t)(n0 + row) * KSTR + koff + c8 * 8);
    }
    cp_commit();
}

__global__ void __launch_bounds__(512, 1) gemm_kernel(
    const float* __restrict__ bias, float* __restrict__ out)
{
    extern __shared__ char smc[];
    const uint32_t sb = smem_to_u32(smc);
    const int tid = threadIdx.x;
    const int lane = tid & 31;
    const int wid = tid >> 5;
    const int wm = wid >> 2;        // 0..3 -> m offset *32
    const int wn = wid & 3;         // 0..3 -> n offset *64
    const int n0 = blockIdx.x * 256;
    const int m0 = blockIdx.y * 128;

    const int jg = lane >> 3, rr = lane & 7;
    const uint32_t xorv = (uint32_t)(rr << 4);
    const uint32_t arow = (uint32_t)((jg & 1) * 8 + rr);
    const uint32_t akb  = (uint32_t)((jg >> 1) * 16);
    const uint32_t brow = (uint32_t)((jg >> 1) * 8 + rr);
    const uint32_t bkb  = (uint32_t)((jg & 1) * 16);

    float acc[2][8][4];
#pragma unroll
    for (int i = 0; i < 2; ++i)
#pragma unroll
        for (int j = 0; j < 8; ++j)
#pragma unroll
            for (int q = 0; q < 4; ++q) acc[i][j][q] = 0.0f;

    m_issue(sb, 0, 0, m0, n0, tid);
    m_issue(sb, 1, 1, m0, n0, tid);
    m_issue(sb, 2, 2, m0, n0, tid);

#pragma unroll 1
    for (int c = 0; c < G_NCH; ++c) {
        const int s = c & 3;
        if (c < G_NCH - 2)       asm volatile("cp.async.wait_group 2;" ::: "memory");
        else if (c == G_NCH - 2) asm volatile("cp.async.wait_group 1;" ::: "memory");
        else                     asm volatile("cp.async.wait_group 0;" ::: "memory");
        __syncthreads();
        if (c + 3 < G_NCH) m_issue(sb, (c + 3) & 3, c + 3, m0, n0, tid);

        const uint32_t sA = sb + s * G_STG;
        const uint32_t sB = sA + G_PA;
#pragma unroll
        for (int k16 = 0; k16 < 4; ++k16) {
            const uint32_t kA = ((uint32_t)(k16 * 32) + akb) ^ xorv;
            const uint32_t kB = ((uint32_t)(k16 * 32) + bkb) ^ xorv;
            uint32_t ah[2][4];
#pragma unroll
            for (int i = 0; i < 2; ++i) {
                uint32_t ro = (uint32_t)((wm * 32 + i * 16 + arow) * 128);
                ldsm4(ah[i], sA + ro + kA);
            }
#pragma unroll
            for (int j2 = 0; j2 < 4; ++j2) {
                uint32_t bh[4];
                uint32_t ro = (uint32_t)((wn * 64 + j2 * 16 + brow) * 128);
                ldsm4(bh, sB + ro + kB);
#pragma unroll
                for (int i = 0; i < 2; ++i) {
                    mma16816(acc[i][j2 * 2],     ah[i], bh);
                    mma16816(acc[i][j2 * 2 + 1], ah[i], bh + 2);
                }
            }
        }
    }

    // Epilogue: bias + fp32 store
    const int gi = lane >> 2;
    const int tg = lane & 3;
#pragma unroll
    for (int j = 0; j < 8; ++j) {
        const int ncol = n0 + wn * 64 + j * 8 + tg * 2;
        const float b0 = bias[ncol], b1 = bias[ncol + 1];
#pragma unroll
        for (int i = 0; i < 2; ++i) {
            const int r0 = m0 + wm * 32 + i * 16 + gi;
            float2 v0 = make_float2(acc[i][j][0] + b0, acc[i][j][1] + b1);
            float2 v1 = make_float2(acc[i][j][2] + b0, acc[i][j][3] + b1);
            *(float2*)(out + (size_t)r0 * D_OUT + ncol) = v0;
            *(float2*)(out + (size_t)(r0 + 8) * D_OUT + ncol) = v1;
        }
    }
}

// ============================================================================
// Launch
// ============================================================================
extern "C" void kernel_launch(void* const* d_in, const int* in_sizes, int n_in,
                              void* d_out, int out_size)
{
    const float* x      = (const float*)d_in[0];
    const float* W      = (const float*)d_in[1];
    const float* bias   = (const float*)d_in[2];
    const float* routeW = (const float*)d_in[3];
    const float* loraA  = (const float*)d_in[4];
    const float* loraB  = (const float*)d_in[5];
    float* out = (float*)d_out;

    const size_t RES = (size_t)T_TOK * D_OUT;
    float* out_rw;
    float* out_gs;
    if ((size_t)out_size >= RES + 2u * T_TOK * N_EXP) {
        out_rw = out + RES;
        out_gs = out_rw + (size_t)T_TOK * N_EXP;
    } else {
        float* dummy;
        cudaGetSymbolAddress((void**)&dummy, g_dummy_rw);
        out_rw = dummy;
        out_gs = dummy + (size_t)T_TOK * N_EXP;
    }

    cudaFuncSetAttribute(gate_kernel,  cudaFuncAttributeMaxDynamicSharedMemorySize, GT_SMEM);
    cudaFuncSetAttribute(hgemm_kernel, cudaFuncAttributeMaxDynamicSharedMemorySize, H_SMEM);
    cudaFuncSetAttribute(gemm_kernel,  cudaFuncAttributeMaxDynamicSharedMemorySize, G_SMEM);

    gate_kernel<<<T_TOK / 64, 256, GT_SMEM>>>(x, routeW, out_rw, out_gs);
    convX_kernel<<<(T_TOK * (D_IN / 4)) / 256, 256>>>(x);
    convW_kernel<<<(D_OUT * (D_IN / 4)) / 256, 256>>>(W);
    convA_kernel<<<(KEXTRA * (D_IN / 4)) / 256, 256>>>(loraA);
    packL_kernel<<<(D_OUT * KEXTRA) / 256, 256>>>(loraB);
    hgemm_kernel<<<T_TOK / 64, 256, H_SMEM>>>();
    gemm_kernel<<<dim3(D_OUT / 256, T_TOK / 128), 512, G_SMEM>>>(bias, out);
}